// round 2
// baseline (speedup 1.0000x reference)
#include <cuda_runtime.h>
#include <cstdint>
#include <math.h>

#define Bn 256
#define Sn 512
#define Hn 64
#define En 330
#define Tn 16
#define Gn 256   // 4H
#define START_IX 14
#define STOP_IX 15
#define NROWS_TOTAL 20868

// ---- scratch (static device memory) ----
__device__ float g_WT[En * 512];                       // Wih transposed+concat [E][512]
__device__ float g_bias[512];
__device__ float g_proj[(size_t)NROWS_TOTAL * 512];    // projected tables  ~42.7MB
__device__ float g_xp[2][(size_t)Sn * Bn * Gn];        // x-projections     2x134MB
__device__ float g_h[2][(size_t)Sn * Bn * Hn];         // lstm hidden       2x33.5MB
__device__ float g_feats[(size_t)Sn * Bn * Tn];        // emissions         8.4MB

// ---- packed f32x2 helpers ----
__device__ __forceinline__ void fma2(unsigned long long& d, unsigned long long a,
                                     unsigned long long b) {
    asm("fma.rn.f32x2 %0, %1, %2, %0;" : "+l"(d) : "l"(a), "l"(b));
}
__device__ __forceinline__ unsigned long long pack2(float a, float b) {
    unsigned long long v;
    asm("mov.b64 %0, {%1,%2};" : "=l"(v) : "f"(a), "f"(b));
    return v;
}
__device__ __forceinline__ float2 unpack2(unsigned long long v) {
    float2 r;
    asm("mov.b64 {%0,%1}, %2;" : "=f"(r.x), "=f"(r.y) : "l"(v));
    return r;
}
__device__ __forceinline__ float tanhfast(float x) {
    float y;
    asm("tanh.approx.f32 %0, %1;" : "=f"(y) : "f"(x));
    return y;
}
__device__ __forceinline__ float sigfast(float x) {
    return fmaf(0.5f, tanhfast(0.5f * x), 0.5f);
}

// ---- K0: transpose Wih_f/Wih_b into [E][512] and fold biases ----
__global__ void prep_kernel(const float* __restrict__ Wf, const float* __restrict__ Wb,
                            const float* __restrict__ bihf, const float* __restrict__ bhhf,
                            const float* __restrict__ bihb, const float* __restrict__ bhhb) {
    int idx = blockIdx.x * blockDim.x + threadIdx.x;
    if (idx < En * 512) {
        int c = idx / 512, j = idx % 512;
        g_WT[idx] = (j < 256) ? Wf[j * En + c] : Wb[(j - 256) * En + c];
    }
    if (idx < 512) {
        g_bias[idx] = (idx < 256) ? (bihf[idx] + bhhf[idx]) : (bihb[idx - 256] + bhhb[idx - 256]);
    }
}

// ---- K1: project ALL embedding tables into g_proj (single launch) ----
// block ranges: word [0,2500), flag [2500,2508), bound [2508,2509),
//               radical [2509,2547), pinyin [2547,2610)
__global__ __launch_bounds__(512)
void proj_all_kernel(const float* __restrict__ word, const float* __restrict__ flag,
                     const float* __restrict__ bound, const float* __restrict__ radical,
                     const float* __restrict__ pinyin) {
    const int bb = blockIdx.x;
    const float* emb;
    int nrows, width, segoff, base, r0;
    if (bb < 2500)      { emb = word;    nrows = 20000; width = 100; segoff = 0;   base = 0;     r0 = bb * 8; }
    else if (bb < 2508) { emb = flag;    nrows = 60;    width = 50;  segoff = 100; base = 20000; r0 = (bb - 2500) * 8; }
    else if (bb < 2509) { emb = bound;   nrows = 8;     width = 50;  segoff = 150; base = 20060; r0 = 0; }
    else if (bb < 2547) { emb = radical; nrows = 300;   width = 50;  segoff = 200; base = 20068; r0 = (bb - 2509) * 8; }
    else                { emb = pinyin;  nrows = 500;   width = 80;  segoff = 250; base = 20368; r0 = (bb - 2547) * 8; }

    const int j = threadIdx.x;             // output column 0..511
    __shared__ __align__(16) float es[8][112];  // row stride 448B (8B aligned)
    for (int i = threadIdx.x; i < 8 * width; i += 512) {
        int rr = i / width, kk = i % width;
        es[rr][kk] = (r0 + rr < nrows) ? emb[(size_t)(r0 + rr) * width + kk] : 0.f;
    }
    __syncthreads();

    unsigned long long acc[8] = {0ull, 0ull, 0ull, 0ull, 0ull, 0ull, 0ull, 0ull};
    const int hw = width >> 1;
    for (int kk = 0; kk < hw; kk++) {
        float w0 = g_WT[(size_t)(segoff + 2 * kk) * 512 + j];
        float w1 = g_WT[(size_t)(segoff + 2 * kk + 1) * 512 + j];
        unsigned long long w2 = pack2(w0, w1);
#pragma unroll
        for (int r = 0; r < 8; r++) {
            unsigned long long h2 = *(const unsigned long long*)&es[r][2 * kk];
            fma2(acc[r], h2, w2);
        }
    }
#pragma unroll
    for (int r = 0; r < 8; r++) {
        if (r0 + r < nrows) {
            float2 u = unpack2(acc[r]);
            g_proj[(size_t)(base + r0 + r) * 512 + j] = u.x + u.y;
        }
    }
}

// ---- K2: gather-sum 5 projected rows + bias -> xproj for both dirs ----
__global__ __launch_bounds__(512)
void gather_kernel(const int* __restrict__ wi, const int* __restrict__ fi,
                   const int* __restrict__ bi, const int* __restrict__ ri,
                   const int* __restrict__ pi) {
    const int sb = blockIdx.x;             // sb = s*B + b
    const int s = sb >> 8, b = sb & 255;
    const int j = threadIdx.x;             // 512
    const int iw = wi[b * Sn + s];
    const int ifl = fi[b * Sn + s];
    const int ib = bi[b * Sn + s];
    const int ir = ri[b * Sn + s];
    const int ip = pi[b * Sn + s];
    float v = g_bias[j]
            + g_proj[(size_t)iw * 512 + j]
            + g_proj[(size_t)(20000 + ifl) * 512 + j]
            + g_proj[(size_t)(20060 + ib) * 512 + j]
            + g_proj[(size_t)(20068 + ir) * 512 + j]
            + g_proj[(size_t)(20368 + ip) * 512 + j];
    if (j < 256) g_xp[0][(size_t)sb * Gn + j] = v;
    else         g_xp[1][(size_t)sb * Gn + (j - 256)] = v;
}

// ---- K3: recurrence. grid (64,2), 256 threads, Bc=4 batch/CTA. packed FFMA2 ----
__global__ __launch_bounds__(256, 1)
void lstm_kernel(const float* __restrict__ Whh_f, const float* __restrict__ Whh_b,
                 const float* __restrict__ h0, const float* __restrict__ c0) {
    const int dir = blockIdx.y;
    const int b0 = blockIdx.x * 4;
    const float* __restrict__ Whh = dir ? Whh_b : Whh_f;
    const float* __restrict__ xp = g_xp[dir];
    float* __restrict__ hout = g_h[dir];
    const int j = threadIdx.x;             // gate-output index 0..255

    // pre-pack the weight row: 32 x u64 (pairs)
    unsigned long long wp[32];
    {
        const ulonglong2* wrow = (const ulonglong2*)(Whh + j * 64);
#pragma unroll
        for (int q = 0; q < 16; q++) { ulonglong2 t = wrow[q]; wp[2 * q] = t.x; wp[2 * q + 1] = t.y; }
    }

    __shared__ __align__(16) float h_sh[4][64];
    __shared__ float z_sh[4][256];

    const int cb = j >> 6, ck = j & 63;    // this thread's cell (batch, hidden)
    float c = c0[dir * Bn * Hn + (b0 + cb) * Hn + ck];
    h_sh[cb][ck] = h0[dir * Bn * Hn + (b0 + cb) * Hn + ck];

    int t = dir ? (Sn - 1) : 0;
    const float* xr = xp + ((size_t)t * Bn + b0) * Gn + j;
    float xc0 = xr[0], xc1 = xr[Gn], xc2 = xr[2 * Gn], xc3 = xr[3 * Gn];
    __syncthreads();

    for (int step = 0; step < Sn; step++) {
        float xn0 = 0.f, xn1 = 0.f, xn2 = 0.f, xn3 = 0.f;
        if (step + 1 < Sn) {
            int tn = dir ? (t - 1) : (t + 1);
            const float* xn = xp + ((size_t)tn * Bn + b0) * Gn + j;
            xn0 = xn[0]; xn1 = xn[Gn]; xn2 = xn[2 * Gn]; xn3 = xn[3 * Gn];
        }
        unsigned long long acc0 = 0ull, acc1 = 0ull, acc2v = 0ull, acc3 = 0ull;
        const ulonglong2* h0p = (const ulonglong2*)h_sh[0];
        const ulonglong2* h1p = (const ulonglong2*)h_sh[1];
        const ulonglong2* h2p = (const ulonglong2*)h_sh[2];
        const ulonglong2* h3p = (const ulonglong2*)h_sh[3];
#pragma unroll
        for (int q = 0; q < 16; q++) {
            ulonglong2 v0 = h0p[q], v1 = h1p[q], v2 = h2p[q], v3 = h3p[q];
            fma2(acc0, v0.x, wp[2 * q]); fma2(acc0, v0.y, wp[2 * q + 1]);
            fma2(acc1, v1.x, wp[2 * q]); fma2(acc1, v1.y, wp[2 * q + 1]);
            fma2(acc2v, v2.x, wp[2 * q]); fma2(acc2v, v2.y, wp[2 * q + 1]);
            fma2(acc3, v3.x, wp[2 * q]); fma2(acc3, v3.y, wp[2 * q + 1]);
        }
        {
            float2 u0 = unpack2(acc0), u1 = unpack2(acc1), u2 = unpack2(acc2v), u3 = unpack2(acc3);
            z_sh[0][j] = xc0 + u0.x + u0.y;
            z_sh[1][j] = xc1 + u1.x + u1.y;
            z_sh[2][j] = xc2 + u2.x + u2.y;
            z_sh[3][j] = xc3 + u3.x + u3.y;
        }
        __syncthreads();

        float zi = z_sh[cb][ck];
        float zf = z_sh[cb][64 + ck];
        float zg = z_sh[cb][128 + ck];
        float zo = z_sh[cb][192 + ck];
        c = sigfast(zf) * c + sigfast(zi) * tanhfast(zg);
        float hh = sigfast(zo) * tanhfast(c);
        h_sh[cb][ck] = hh;
        hout[((size_t)t * Bn + b0 + cb) * Hn + ck] = hh;
        __syncthreads();

        xc0 = xn0; xc1 = xn1; xc2 = xn2; xc3 = xn3;
        t = dir ? (t - 1) : (t + 1);
    }
}

// ---- K4: emissions feats = [hf|hb] @ Wout^T + bout ----
__global__ void feats_kernel(const float* __restrict__ Wout, const float* __restrict__ bout) {
    const int p = blockIdx.x * 16 + (threadIdx.x >> 4);  // sb index
    const int jj = threadIdx.x & 15;
    const float* hf = g_h[0] + (size_t)p * Hn;
    const float* hb = g_h[1] + (size_t)p * Hn;
    const float* w0 = Wout + jj * 128;
    float acc = bout[jj];
#pragma unroll 8
    for (int k = 0; k < 64; k++) acc = fmaf(hf[k], w0[k], fmaf(hb[k], w0[64 + k], acc));
    g_feats[(size_t)p * Tn + jj] = acc;
}

// ---- K5: CRF forward algorithm + real path score -> loss ----
__global__ __launch_bounds__(128)
void crf_kernel(const float* __restrict__ transitions,
                const int* __restrict__ tags, float* __restrict__ out) {
    const int b = blockIdx.x * 8 + (threadIdx.x >> 4);
    const int n = threadIdx.x & 15;        // "next" tag this lane owns
    const unsigned FULL = 0xFFFFFFFFu;

    float tr[16];
#pragma unroll
    for (int k = 0; k < 16; k++) tr[k] = transitions[n * 16 + k];
    float tmax = tr[0];
#pragma unroll
    for (int k = 1; k < 16; k++) tmax = fmaxf(tmax, tr[k]);
    float expT[16];
#pragma unroll
    for (int k = 0; k < 16; k++) expT[k] = __expf(tr[k] - tmax);

    float alpha = (n == START_IX) ? 0.f : -10000.f;
    float feat = g_feats[((size_t)0 * Bn + b) * Tn + n];
    for (int s = 0; s < Sn; s++) {
        float feat_nx = 0.f;
        if (s + 1 < Sn) feat_nx = g_feats[((size_t)(s + 1) * Bn + b) * Tn + n];
        float m = alpha;
#pragma unroll
        for (int o = 8; o; o >>= 1) m = fmaxf(m, __shfl_xor_sync(FULL, m, o, 16));
        float e = __expf(alpha - m);
        float acc_a = 0.f, acc_b = 0.f;
#pragma unroll
        for (int k = 0; k < 16; k += 2) {
            acc_a = fmaf(__shfl_sync(FULL, e, k, 16), expT[k], acc_a);
            acc_b = fmaf(__shfl_sync(FULL, e, k + 1, 16), expT[k + 1], acc_b);
        }
        alpha = feat + m + tmax + __logf(acc_a + acc_b);
        feat = feat_nx;
    }
    // all-path score: LSE(alpha + trans[STOP,:])
    float v = alpha + transitions[STOP_IX * 16 + n];
    float m2 = v;
#pragma unroll
    for (int o = 8; o; o >>= 1) m2 = fmaxf(m2, __shfl_xor_sync(FULL, m2, o, 16));
    float se = __expf(v - m2);
#pragma unroll
    for (int o = 8; o; o >>= 1) se += __shfl_xor_sync(FULL, se, o, 16);
    float all_sc = m2 + __logf(se);

    // real path score: lanes stride over s
    float rp = 0.f;
    for (int s = n; s < Sn; s += 16) {
        int tg = tags[b * Sn + s];
        int pv = (s == 0) ? START_IX : tags[b * Sn + s - 1];
        rp += g_feats[((size_t)s * Bn + b) * Tn + tg] + transitions[tg * 16 + pv];
    }
#pragma unroll
    for (int o = 8; o; o >>= 1) rp += __shfl_xor_sync(FULL, rp, o, 16);

    if (n == 0) {
        float real = rp + transitions[STOP_IX * 16 + tags[b * Sn + Sn - 1]];
        out[b] = all_sc - real;
    }
}

extern "C" void kernel_launch(void* const* d_in, const int* in_sizes, int n_in,
                              void* d_out, int out_size) {
    const float* word_emb    = (const float*)d_in[0];
    const float* flag_emb    = (const float*)d_in[1];
    const float* bound_emb   = (const float*)d_in[2];
    const float* radical_emb = (const float*)d_in[3];
    const float* pinyin_emb  = (const float*)d_in[4];
    const float* Wih_f = (const float*)d_in[5];
    const float* Whh_f = (const float*)d_in[6];
    const float* bih_f = (const float*)d_in[7];
    const float* bhh_f = (const float*)d_in[8];
    const float* Wih_b = (const float*)d_in[9];
    const float* Whh_b = (const float*)d_in[10];
    const float* bih_b = (const float*)d_in[11];
    const float* bhh_b = (const float*)d_in[12];
    const float* Wout  = (const float*)d_in[13];
    const float* bout  = (const float*)d_in[14];
    const float* transitions = (const float*)d_in[15];
    const float* h0 = (const float*)d_in[16];
    const float* c0 = (const float*)d_in[17];
    const int* word_ids    = (const int*)d_in[18];
    const int* flag_ids    = (const int*)d_in[19];
    const int* bound_ids   = (const int*)d_in[20];
    const int* radical_ids = (const int*)d_in[21];
    const int* pinyin_ids  = (const int*)d_in[22];
    const int* tags        = (const int*)d_in[23];

    prep_kernel<<<(En * 512 + 255) / 256, 256>>>(Wih_f, Wih_b, bih_f, bhh_f, bih_b, bhh_b);

    proj_all_kernel<<<2610, 512>>>(word_emb, flag_emb, bound_emb, radical_emb, pinyin_emb);

    gather_kernel<<<Sn * Bn, 512>>>(word_ids, flag_ids, bound_ids, radical_ids, pinyin_ids);

    dim3 lgrid(64, 2);
    lstm_kernel<<<lgrid, 256>>>(Whh_f, Whh_b, h0, c0);

    feats_kernel<<<Sn * Bn / 16, 256>>>(Wout, bout);

    crf_kernel<<<Bn / 8, 128>>>(transitions, tags, (float*)d_out);
}

// round 3
// speedup vs baseline: 2.4173x; 2.4173x over previous
#include <cuda_runtime.h>
#include <cstdint>
#include <math.h>

#define Bn 256
#define Sn 512
#define Hn 64
#define En 330
#define Tn 16
#define Gn 256   // 4H
#define START_IX 14
#define STOP_IX 15
#define NROWS_TOTAL 20868

// ---- scratch (static device memory) ----
__device__ float g_WT[En * 512];                       // Wih transposed+concat [E][512]
__device__ float g_bias[512];
__device__ float g_proj[(size_t)NROWS_TOTAL * 512];    // projected tables  ~42.7MB
__device__ float g_xp[2][(size_t)Sn * Bn * Gn];        // x-projections     2x134MB
__device__ float g_h[2][(size_t)Sn * Bn * Hn];         // lstm hidden       2x33.5MB
__device__ float g_feats[(size_t)Sn * Bn * Tn];        // emissions         8.4MB

// ---- packed f32x2 helpers ----
__device__ __forceinline__ void fma2(unsigned long long& d, unsigned long long a,
                                     unsigned long long b) {
    asm("fma.rn.f32x2 %0, %1, %2, %0;" : "+l"(d) : "l"(a), "l"(b));
}
__device__ __forceinline__ unsigned long long pack2(float a, float b) {
    unsigned long long v;
    asm("mov.b64 %0, {%1,%2};" : "=l"(v) : "f"(a), "f"(b));
    return v;
}
__device__ __forceinline__ float2 unpack2(unsigned long long v) {
    float2 r;
    asm("mov.b64 {%0,%1}, %2;" : "=f"(r.x), "=f"(r.y) : "l"(v));
    return r;
}
__device__ __forceinline__ float tanhfast(float x) {
    float y;
    asm("tanh.approx.f32 %0, %1;" : "=f"(y) : "f"(x));
    return y;
}
__device__ __forceinline__ float sigfast(float x) {
    return fmaf(0.5f, tanhfast(0.5f * x), 0.5f);
}

// ---- K0: transpose Wih_f/Wih_b into [E][512] and fold biases ----
__global__ void prep_kernel(const float* __restrict__ Wf, const float* __restrict__ Wb,
                            const float* __restrict__ bihf, const float* __restrict__ bhhf,
                            const float* __restrict__ bihb, const float* __restrict__ bhhb) {
    int idx = blockIdx.x * blockDim.x + threadIdx.x;
    if (idx < En * 512) {
        int c = idx / 512, j = idx % 512;
        g_WT[idx] = (j < 256) ? Wf[j * En + c] : Wb[(j - 256) * En + c];
    }
    if (idx < 512) {
        g_bias[idx] = (idx < 256) ? (bihf[idx] + bhhf[idx]) : (bihb[idx - 256] + bhhb[idx - 256]);
    }
}

// ---- K1: project ALL embedding tables into g_proj (single launch) ----
__global__ __launch_bounds__(512)
void proj_all_kernel(const float* __restrict__ word, const float* __restrict__ flag,
                     const float* __restrict__ bound, const float* __restrict__ radical,
                     const float* __restrict__ pinyin) {
    const int bb = blockIdx.x;
    const float* emb;
    int nrows, width, segoff, base, r0;
    if (bb < 2500)      { emb = word;    nrows = 20000; width = 100; segoff = 0;   base = 0;     r0 = bb * 8; }
    else if (bb < 2508) { emb = flag;    nrows = 60;    width = 50;  segoff = 100; base = 20000; r0 = (bb - 2500) * 8; }
    else if (bb < 2509) { emb = bound;   nrows = 8;     width = 50;  segoff = 150; base = 20060; r0 = 0; }
    else if (bb < 2547) { emb = radical; nrows = 300;   width = 50;  segoff = 200; base = 20068; r0 = (bb - 2509) * 8; }
    else                { emb = pinyin;  nrows = 500;   width = 80;  segoff = 250; base = 20368; r0 = (bb - 2547) * 8; }

    const int j = threadIdx.x;             // output column 0..511
    __shared__ __align__(16) float es[8][112];
    for (int i = threadIdx.x; i < 8 * width; i += 512) {
        int rr = i / width, kk = i % width;
        es[rr][kk] = (r0 + rr < nrows) ? emb[(size_t)(r0 + rr) * width + kk] : 0.f;
    }
    __syncthreads();

    unsigned long long acc[8] = {0ull, 0ull, 0ull, 0ull, 0ull, 0ull, 0ull, 0ull};
    const int hw = width >> 1;
    for (int kk = 0; kk < hw; kk++) {
        float w0 = g_WT[(size_t)(segoff + 2 * kk) * 512 + j];
        float w1 = g_WT[(size_t)(segoff + 2 * kk + 1) * 512 + j];
        unsigned long long w2 = pack2(w0, w1);
#pragma unroll
        for (int r = 0; r < 8; r++) {
            unsigned long long h2 = *(const unsigned long long*)&es[r][2 * kk];
            fma2(acc[r], h2, w2);
        }
    }
#pragma unroll
    for (int r = 0; r < 8; r++) {
        if (r0 + r < nrows) {
            float2 u = unpack2(acc[r]);
            g_proj[(size_t)(base + r0 + r) * 512 + j] = u.x + u.y;
        }
    }
}

// ---- K2: gather-sum, float4 vectorized, 4 positions per block ----
__global__ __launch_bounds__(128)
void gather_kernel(const int* __restrict__ wi, const int* __restrict__ fi,
                   const int* __restrict__ bi, const int* __restrict__ ri,
                   const int* __restrict__ pi) {
    const int t = threadIdx.x;             // 0..127, covers float4 lane
    const float4 bias4 = *(const float4*)(g_bias + 4 * t);
#pragma unroll
    for (int pos = 0; pos < 4; pos++) {
        const int sb = blockIdx.x * 4 + pos;   // sb = s*B + b
        const int s = sb >> 8, b = sb & 255;
        const int iw  = wi[b * Sn + s];
        const int ifl = fi[b * Sn + s];
        const int ib  = bi[b * Sn + s];
        const int ir  = ri[b * Sn + s];
        const int ip  = pi[b * Sn + s];
        float4 v = bias4;
        float4 a0 = *(const float4*)(g_proj + (size_t)iw * 512 + 4 * t);
        float4 a1 = *(const float4*)(g_proj + (size_t)(20000 + ifl) * 512 + 4 * t);
        float4 a2 = *(const float4*)(g_proj + (size_t)(20060 + ib) * 512 + 4 * t);
        float4 a3 = *(const float4*)(g_proj + (size_t)(20068 + ir) * 512 + 4 * t);
        float4 a4 = *(const float4*)(g_proj + (size_t)(20368 + ip) * 512 + 4 * t);
        v.x += a0.x + a1.x + a2.x + a3.x + a4.x;
        v.y += a0.y + a1.y + a2.y + a3.y + a4.y;
        v.z += a0.z + a1.z + a2.z + a3.z + a4.z;
        v.w += a0.w + a1.w + a2.w + a3.w + a4.w;
        if (t < 64) *(float4*)(g_xp[0] + (size_t)sb * Gn + 4 * t) = v;
        else        *(float4*)(g_xp[1] + (size_t)sb * Gn + 4 * t - 256) = v;
    }
}

// ---- K3: recurrence. grid (128,2)=256 CTAs, 256 thr, Bc=2, 2 CTAs/SM ----
__global__ __launch_bounds__(256, 2)
void lstm_kernel(const float* __restrict__ Whh_f, const float* __restrict__ Whh_b,
                 const float* __restrict__ h0, const float* __restrict__ c0) {
    const int dir = blockIdx.y;
    const int b0 = blockIdx.x * 2;
    const float* __restrict__ Whh = dir ? Whh_b : Whh_f;
    const float* __restrict__ xp = g_xp[dir];
    float* __restrict__ hout = g_h[dir];
    const int j = threadIdx.x;             // gate-output index 0..255

    unsigned long long wp[32];
    {
        const ulonglong2* wrow = (const ulonglong2*)(Whh + j * 64);
#pragma unroll
        for (int q = 0; q < 16; q++) { ulonglong2 t2 = wrow[q]; wp[2 * q] = t2.x; wp[2 * q + 1] = t2.y; }
    }

    __shared__ __align__(16) float h_sh[2][64];
    __shared__ float z_sh[2][256];

    const int cb = (j >> 6) & 1, ck = j & 63;
    float c = 0.f;
    if (j < 128) {
        c = c0[dir * Bn * Hn + (b0 + cb) * Hn + ck];
        h_sh[cb][ck] = h0[dir * Bn * Hn + (b0 + cb) * Hn + ck];
    }

    int t = dir ? (Sn - 1) : 0;
    const float* xr = xp + ((size_t)t * Bn + b0) * Gn + j;
    float xc0 = xr[0], xc1 = xr[Gn];
    __syncthreads();

    for (int step = 0; step < Sn; step++) {
        float xn0 = 0.f, xn1 = 0.f;
        if (step + 1 < Sn) {
            int tn = dir ? (t - 1) : (t + 1);
            const float* xn = xp + ((size_t)tn * Bn + b0) * Gn + j;
            xn0 = xn[0]; xn1 = xn[Gn];
        }
        unsigned long long acc0 = 0ull, acc1 = 0ull;
        const ulonglong2* h0p = (const ulonglong2*)h_sh[0];
        const ulonglong2* h1p = (const ulonglong2*)h_sh[1];
#pragma unroll
        for (int q = 0; q < 16; q++) {
            ulonglong2 v0 = h0p[q], v1 = h1p[q];
            fma2(acc0, v0.x, wp[2 * q]); fma2(acc0, v0.y, wp[2 * q + 1]);
            fma2(acc1, v1.x, wp[2 * q]); fma2(acc1, v1.y, wp[2 * q + 1]);
        }
        {
            float2 u0 = unpack2(acc0), u1 = unpack2(acc1);
            z_sh[0][j] = xc0 + u0.x + u0.y;
            z_sh[1][j] = xc1 + u1.x + u1.y;
        }
        __syncthreads();

        if (j < 128) {
            float zi = z_sh[cb][ck];
            float zf = z_sh[cb][64 + ck];
            float zg = z_sh[cb][128 + ck];
            float zo = z_sh[cb][192 + ck];
            c = sigfast(zf) * c + sigfast(zi) * tanhfast(zg);
            float hh = sigfast(zo) * tanhfast(c);
            h_sh[cb][ck] = hh;
            hout[((size_t)t * Bn + b0 + cb) * Hn + ck] = hh;
        }
        __syncthreads();

        xc0 = xn0; xc1 = xn1;
        t = dir ? (t - 1) : (t + 1);
    }
}

// ---- K4: emissions, SMEM-staged, 32 positions per 512-thread block ----
__global__ __launch_bounds__(512)
void feats_kernel(const float* __restrict__ Wout, const float* __restrict__ bout) {
    const int p0 = blockIdx.x * 32;
    const int tid = threadIdx.x;
    __shared__ __align__(16) float hs[32][132];   // [pos][0:64)=hf, [64:128)=hb
    __shared__ __align__(16) float ws[16 * 132];  // Wout rows, padded stride 132
    __shared__ float bs[16];

    // load Wout (16x128) into padded smem rows
    {
        int f = tid * 4;                 // 0..2044
        if (f < 2048) {
            float4 w4 = *(const float4*)(Wout + f);
            int row = f >> 7, off = f & 127;
            *(float4*)&ws[row * 132 + off] = w4;
        }
        if (tid < 16) bs[tid] = bout[tid];
    }
    // load h, coalesced float4
    {
        int f = tid * 4;                 // 0..2044 covers 32 pos x 64 floats
        float4 hf4 = *(const float4*)(g_h[0] + (size_t)p0 * Hn + f);
        float4 hb4 = *(const float4*)(g_h[1] + (size_t)p0 * Hn + f);
        int pos = f >> 6, off = f & 63;
        *(float4*)&hs[pos][off] = hf4;
        *(float4*)&hs[pos][64 + off] = hb4;
    }
    __syncthreads();

    const int pos = tid >> 4, tag = tid & 15;
    const float4* hv = (const float4*)&hs[pos][0];
    const float4* wv = (const float4*)&ws[tag * 132];
    float acc0 = bs[tag], acc1 = 0.f;
#pragma unroll
    for (int k = 0; k < 32; k += 2) {
        float4 a = hv[k], b = wv[k];
        float4 a2 = hv[k + 1], b2 = wv[k + 1];
        acc0 = fmaf(a.x, b.x, fmaf(a.y, b.y, acc0));
        acc1 = fmaf(a.z, b.z, fmaf(a.w, b.w, acc1));
        acc0 = fmaf(a2.x, b2.x, fmaf(a2.y, b2.y, acc0));
        acc1 = fmaf(a2.z, b2.z, fmaf(a2.w, b2.w, acc1));
    }
    g_feats[(size_t)(p0 + pos) * Tn + tag] = acc0 + acc1;
}

// ---- K5: CRF forward + real path -> loss. 128 blocks x 32 thr ----
__global__ __launch_bounds__(32)
void crf_kernel(const float* __restrict__ transitions,
                const int* __restrict__ tags, float* __restrict__ out) {
    const int b = blockIdx.x * 2 + (threadIdx.x >> 4);
    const int n = threadIdx.x & 15;        // "next" tag this lane owns
    const unsigned FULL = 0xFFFFFFFFu;

    float expT[16];
#pragma unroll
    for (int k = 0; k < 16; k++) expT[k] = __expf(transitions[n * 16 + k]);

    // step 0 analytic: alpha = feats[0] + T[n, START]  (exact in fp32)
    float alpha = g_feats[(size_t)b * Tn + n] + transitions[n * 16 + START_IX];
    float feat = g_feats[((size_t)1 * Bn + b) * Tn + n];

    for (int s = 1; s < Sn; s++) {
        float feat_nx = 0.f;
        if (s + 1 < Sn) feat_nx = g_feats[((size_t)(s + 1) * Bn + b) * Tn + n];
        // m = lane-0 alpha of this 16-group (normal tag; spread of normal alphas is small)
        float m = __shfl_sync(FULL, alpha, 0, 16);
        float e = __expf(alpha - m);
        float acc_a = 0.f, acc_b = 0.f;
#pragma unroll
        for (int k = 0; k < 16; k += 2) {
            acc_a = fmaf(__shfl_sync(FULL, e, k, 16), expT[k], acc_a);
            acc_b = fmaf(__shfl_sync(FULL, e, k + 1, 16), expT[k + 1], acc_b);
        }
        alpha = feat + m + __logf(acc_a + acc_b);
        feat = feat_nx;
    }
    // all-path score: exact LSE(alpha + trans[STOP,:])
    float v = alpha + transitions[STOP_IX * 16 + n];
    float m2 = v;
#pragma unroll
    for (int o = 8; o; o >>= 1) m2 = fmaxf(m2, __shfl_xor_sync(FULL, m2, o, 16));
    float se = __expf(v - m2);
#pragma unroll
    for (int o = 8; o; o >>= 1) se += __shfl_xor_sync(FULL, se, o, 16);
    float all_sc = m2 + __logf(se);

    // real path score: lanes stride over s
    float rp = 0.f;
    for (int s = n; s < Sn; s += 16) {
        int tg = tags[b * Sn + s];
        int pv = (s == 0) ? START_IX : tags[b * Sn + s - 1];
        rp += g_feats[((size_t)s * Bn + b) * Tn + tg] + transitions[tg * 16 + pv];
    }
#pragma unroll
    for (int o = 8; o; o >>= 1) rp += __shfl_xor_sync(FULL, rp, o, 16);

    if (n == 0) {
        float real = rp + transitions[STOP_IX * 16 + tags[b * Sn + Sn - 1]];
        out[b] = all_sc - real;
    }
}

extern "C" void kernel_launch(void* const* d_in, const int* in_sizes, int n_in,
                              void* d_out, int out_size) {
    const float* word_emb    = (const float*)d_in[0];
    const float* flag_emb    = (const float*)d_in[1];
    const float* bound_emb   = (const float*)d_in[2];
    const float* radical_emb = (const float*)d_in[3];
    const float* pinyin_emb  = (const float*)d_in[4];
    const float* Wih_f = (const float*)d_in[5];
    const float* Whh_f = (const float*)d_in[6];
    const float* bih_f = (const float*)d_in[7];
    const float* bhh_f = (const float*)d_in[8];
    const float* Wih_b = (const float*)d_in[9];
    const float* Whh_b = (const float*)d_in[10];
    const float* bih_b = (const float*)d_in[11];
    const float* bhh_b = (const float*)d_in[12];
    const float* Wout  = (const float*)d_in[13];
    const float* bout  = (const float*)d_in[14];
    const float* transitions = (const float*)d_in[15];
    const float* h0 = (const float*)d_in[16];
    const float* c0 = (const float*)d_in[17];
    const int* word_ids    = (const int*)d_in[18];
    const int* flag_ids    = (const int*)d_in[19];
    const int* bound_ids   = (const int*)d_in[20];
    const int* radical_ids = (const int*)d_in[21];
    const int* pinyin_ids  = (const int*)d_in[22];
    const int* tags        = (const int*)d_in[23];

    prep_kernel<<<(En * 512 + 255) / 256, 256>>>(Wih_f, Wih_b, bih_f, bhh_f, bih_b, bhh_b);

    proj_all_kernel<<<2610, 512>>>(word_emb, flag_emb, bound_emb, radical_emb, pinyin_emb);

    gather_kernel<<<Sn * Bn / 4, 128>>>(word_ids, flag_ids, bound_ids, radical_ids, pinyin_ids);

    dim3 lgrid(128, 2);
    lstm_kernel<<<lgrid, 256>>>(Whh_f, Whh_b, h0, c0);

    feats_kernel<<<Sn * Bn / 32, 512>>>(Wout, bout);

    crf_kernel<<<Bn / 2, 32>>>(transitions, tags, (float*)d_out);
}